// round 10
// baseline (speedup 1.0000x reference)
#include <cuda_runtime.h>
#include <cstdint>
#include <math_constants.h>

// LinkedCrossEntropy, single fused kernel, 2 warps per row:
//   pred    = argmax(y_pred, axis=1)                (first occurrence on ties)
//   penalty = 2 if (pred != y_true && link[y_true, pred]) else 1
//   nll     = -(x[t] - max - log(sum exp(x - max)))
//   out[0]  = mean(penalty * weight[t] * nll)
//
// y_pred: [B, C] f32, y_true: [B] i32, weight: [C] f32, link: [C,C] int32.
// B = 65536, C = 1000.
//
// R9: resubmit of R7 design (R8 bench died to container infra, no signal).
// Rationale (R6 profile): occ=48.5% (48 regs, 5 blk/SM), DRAM=67% ->
// latency bound. 2 warps per row: 16-reg buffer each, exact LSE merge of
// halves, __launch_bounds__(256,6). Expect occ ~75%, DRAM ~85%, ~41us.

#define LCE_C     1000
#define LCE_VEC   (LCE_C / 4)       // 250 float4 per row
#define HALF_VEC  (LCE_VEC / 2)     // 125 float4 per half-row
#define WARPS_PER_BLOCK 8
#define ROWS_PER_BLOCK  (WARPS_PER_BLOCK / 2)   // 4

__device__ double       g_lce_acc;    // zero-init at load; reset by last block
__device__ unsigned int g_lce_count;

__global__ __launch_bounds__(WARPS_PER_BLOCK * 32, 6)
void lce_main_kernel(const float* __restrict__ y_pred,
                     const int* __restrict__ y_true,
                     const float* __restrict__ weight,
                     const int* __restrict__ link,
                     float* __restrict__ out,
                     int B, float inv_b)
{
    const int warp   = threadIdx.x >> 5;
    const int lane   = threadIdx.x & 31;
    const int rowblk = warp >> 1;                 // 0..3
    const int half   = warp & 1;                  // 0 or 1
    const int row    = blockIdx.x * ROWS_PER_BLOCK + rowblk;

    __shared__ float s_m [ROWS_PER_BLOCK][2];
    __shared__ int   s_am[ROWS_PER_BLOCK][2];
    __shared__ float s_s [ROWS_PER_BLOCK][2];
    __shared__ float s_rowloss[ROWS_PER_BLOCK];

    if (row < B) {
        const float4* rp = reinterpret_cast<const float4*>(
            y_pred + (size_t)row * LCE_C) + half * HALF_VEC;

        // ---- load half-row: 4 independent LDG.128 per lane (125 float4) ----
        float4 d[4];
        #pragma unroll
        for (int k = 0; k < 4; k++) {
            int v = lane + 32 * k;
            if (v < HALF_VEC) {
                d[k] = rp[v];
            } else {
                d[k] = make_float4(-CUDART_INF_F, -CUDART_INF_F,
                                   -CUDART_INF_F, -CUDART_INF_F);
            }
        }

        // ---- per-lane max + argmax (strict '>' keeps first index) ----
        const int ibase0 = 4 * (half * HALF_VEC + lane);
        float m = -CUDART_INF_F;
        int   am = 0x7fffffff;
        #pragma unroll
        for (int k = 0; k < 4; k++) {
            int base = ibase0 + 4 * 32 * k;
            float4 x = d[k];
            if (x.x > m) { m = x.x; am = base;     }
            if (x.y > m) { m = x.y; am = base + 1; }
            if (x.z > m) { m = x.z; am = base + 2; }
            if (x.w > m) { m = x.w; am = base + 3; }
        }

        // ---- warp reduce (max, first-index argmax) ----
        #pragma unroll
        for (int off = 16; off > 0; off >>= 1) {
            float mo = __shfl_xor_sync(0xffffffffu, m,  off);
            int   ao = __shfl_xor_sync(0xffffffffu, am, off);
            if (mo > m || (mo == m && ao < am)) { m = mo; am = ao; }
        }

        // ---- sum exp(x - m) from registers ----
        float s = 0.0f;
        #pragma unroll
        for (int k = 0; k < 4; k++) {
            float4 x = d[k];
            s += __expf(x.x - m);
            s += __expf(x.y - m);
            s += __expf(x.z - m);
            s += __expf(x.w - m);
        }
        #pragma unroll
        for (int off = 16; off > 0; off >>= 1)
            s += __shfl_xor_sync(0xffffffffu, s, off);

        if (lane == 0) {
            s_m [rowblk][half] = m;
            s_am[rowblk][half] = am;
            s_s [rowblk][half] = s;
        }
    }
    __syncthreads();

    // ---- one thread per row: merge halves, gather target, penalty ----
    if (threadIdx.x < ROWS_PER_BLOCK) {
        const int r = blockIdx.x * ROWS_PER_BLOCK + threadIdx.x;
        float loss = 0.0f;
        if (r < B) {
            float m0 = s_m[threadIdx.x][0], m1 = s_m[threadIdx.x][1];
            float s0 = s_s[threadIdx.x][0], s1 = s_s[threadIdx.x][1];
            int  am0 = s_am[threadIdx.x][0], am1 = s_am[threadIdx.x][1];

            float m  = fmaxf(m0, m1);
            // exact LSE merge of the two halves
            float s  = s0 * __expf(m0 - m) + s1 * __expf(m1 - m);
            // half 0 wins ties -> first-occurrence argmax preserved
            int   am = (m1 > m0) ? am1 : am0;

            int t = y_true[r];
            float xt = __ldg(y_pred + (size_t)r * LCE_C + t);   // L2 hit
            float nll = (m - xt) + __logf(s);
            float w = weight[t];
            float pen = (am != t && link[(size_t)t * LCE_C + am] != 0)
                        ? 2.0f : 1.0f;
            loss = pen * w * nll;
        }
        s_rowloss[threadIdx.x] = loss;
    }
    __syncthreads();

    // ---- one double atomic per block + last-block finalize ----
    if (threadIdx.x == 0) {
        float bsum = 0.0f;
        #pragma unroll
        for (int r = 0; r < ROWS_PER_BLOCK; r++) bsum += s_rowloss[r];

        atomicAdd(&g_lce_acc, (double)bsum);
        __threadfence();
        unsigned int done = atomicAdd(&g_lce_count, 1u);
        if (done == gridDim.x - 1) {
            double total = atomicAdd(&g_lce_acc, 0.0);   // ordered read
            out[0] = (float)(total * (double)inv_b);
            g_lce_acc   = 0.0;                            // reset for next replay
            g_lce_count = 0u;
            __threadfence();
        }
    }
}

extern "C" void kernel_launch(void* const* d_in, const int* in_sizes, int n_in,
                              void* d_out, int out_size)
{
    const float* y_pred = (const float*)d_in[0];
    const int*   y_true = (const int*)d_in[1];
    const float* weight = (const float*)d_in[2];
    const int*   link   = (const int*)d_in[3];
    float* out = (float*)d_out;

    const int B = in_sizes[1];   // 65536

    int grid = (B + ROWS_PER_BLOCK - 1) / ROWS_PER_BLOCK;
    lce_main_kernel<<<grid, WARPS_PER_BLOCK * 32>>>(
        y_pred, y_true, weight, link, out, B, 1.0f / (float)B);
}

// round 14
// speedup vs baseline: 1.0739x; 1.0739x over previous
#include <cuda_runtime.h>
#include <cstdint>
#include <math_constants.h>

// LinkedCrossEntropy, single fused kernel, 1 warp per row (R6 skeleton):
//   pred    = argmax(y_pred, axis=1)                (first occurrence on ties)
//   penalty = 2 if (pred != y_true && link[y_true, pred]) else 1
//   nll     = -(x[t] - max - log(sum exp(x - max)))
//   out[0]  = mean(penalty * weight[t] * nll)
//
// y_pred: [B, C] f32, y_true: [B] i32, weight: [C] f32, link: [C,C] int32.
// B = 65536, C = 1000.
//
// R10: R7's occupancy push regressed (51.2->55.8us, DRAM 67->62%): binder is
// per-warp dependent-chain latency, not warp count. Revert to 1 warp/row and
// (a) split max/argmax into 4 parallel chains (32-step serial -> 8-step x4),
// (b) 4 parallel exp-sum accumulators, (c) fold exp to FFMA+MUFU via
// ex2(x*log2e - m*log2e). Expect ~45us, DRAM ~75%.

#define LCE_C    1000
#define LCE_VEC  (LCE_C / 4)       // 250 float4 per row
#define WARPS_PER_BLOCK 8

__device__ double       g_lce_acc;    // zero-init at load; reset by last block
__device__ unsigned int g_lce_count;

__device__ __forceinline__ float ex2_approx(float x) {
    float r;
    asm("ex2.approx.f32 %0, %1;" : "=f"(r) : "f"(x));
    return r;
}

__global__ __launch_bounds__(WARPS_PER_BLOCK * 32)
void lce_main_kernel(const float* __restrict__ y_pred,
                     const int* __restrict__ y_true,
                     const float* __restrict__ weight,
                     const int* __restrict__ link,
                     float* __restrict__ out,
                     int B, float inv_b)
{
    const int warp = threadIdx.x >> 5;
    const int lane = threadIdx.x & 31;
    const int row  = blockIdx.x * WARPS_PER_BLOCK + warp;

    __shared__ float s_loss[WARPS_PER_BLOCK];

    float loss = 0.0f;

    if (row < B) {
        const float4* rp = reinterpret_cast<const float4*>(
            y_pred + (size_t)row * LCE_C);

        // ---- load full row into registers: 8 independent LDG.128 per lane ----
        float4 d[8];
        #pragma unroll
        for (int k = 0; k < 8; k++) {
            int v = lane + 32 * k;
            if (v < LCE_VEC) {
                d[k] = rp[v];
            } else {
                d[k] = make_float4(-CUDART_INF_F, -CUDART_INF_F,
                                   -CUDART_INF_F, -CUDART_INF_F);
            }
        }

        // ---- pass 1: FOUR parallel max/argmax chains (one per component).
        //      Within a chain, strict '>' keeps the earliest k (smallest idx).
        float m0 = d[0].x, m1 = d[0].y, m2 = d[0].z, m3 = d[0].w;
        int   b0 = 4 * lane;
        int   a0 = b0, a1 = b0 + 1, a2 = b0 + 2, a3 = b0 + 3;
        #pragma unroll
        for (int k = 1; k < 8; k++) {
            int base = 4 * (lane + 32 * k);
            float4 x = d[k];
            if (x.x > m0) { m0 = x.x; a0 = base;     }
            if (x.y > m1) { m1 = x.y; a1 = base + 1; }
            if (x.z > m2) { m2 = x.z; a2 = base + 2; }
            if (x.w > m3) { m3 = x.w; a3 = base + 3; }
        }
        // cross-chain merge with exact index tie-break (first occurrence)
        float m = m0; int am = a0;
        if (m1 > m || (m1 == m && a1 < am)) { m = m1; am = a1; }
        if (m2 > m || (m2 == m && a2 < am)) { m = m2; am = a2; }
        if (m3 > m || (m3 == m && a3 < am)) { m = m3; am = a3; }

        // ---- warp reduce (max, first-index argmax) ----
        #pragma unroll
        for (int off = 16; off > 0; off >>= 1) {
            float mo = __shfl_xor_sync(0xffffffffu, m,  off);
            int   ao = __shfl_xor_sync(0xffffffffu, am, off);
            if (mo > m || (mo == m && ao < am)) { m = mo; am = ao; }
        }

        // ---- pass 2: sum exp(x-m) = sum ex2(x*log2e - c), c = m*log2e.
        //      FOUR parallel accumulators; FFMA + MUFU per element.
        const float LOG2E = 1.4426950408889634f;
        const float c = m * LOG2E;
        float s0 = 0.0f, s1 = 0.0f, s2 = 0.0f, s3 = 0.0f;
        #pragma unroll
        for (int k = 0; k < 8; k++) {
            float4 x = d[k];
            s0 += ex2_approx(fmaf(x.x, LOG2E, -c));
            s1 += ex2_approx(fmaf(x.y, LOG2E, -c));
            s2 += ex2_approx(fmaf(x.z, LOG2E, -c));
            s3 += ex2_approx(fmaf(x.w, LOG2E, -c));
        }
        float s = (s0 + s1) + (s2 + s3);
        #pragma unroll
        for (int off = 16; off > 0; off >>= 1)
            s += __shfl_xor_sync(0xffffffffu, s, off);

        // ---- lane 0: gather target logit, weight, link penalty ----
        if (lane == 0) {
            int t = y_true[row];
            float xt = __ldg(y_pred + (size_t)row * LCE_C + t);   // L1 hit
            float nll = (m - xt) + __logf(s);
            float w = weight[t];
            float pen = (am != t && link[(size_t)t * LCE_C + am] != 0)
                        ? 2.0f : 1.0f;
            loss = pen * w * nll;
        }
    }

    // ---- block reduce: 8 warp losses, one double atomic per block ----
    if (lane == 0) s_loss[warp] = loss;
    __syncthreads();

    if (threadIdx.x == 0) {
        float bsum = 0.0f;
        #pragma unroll
        for (int w = 0; w < WARPS_PER_BLOCK; w++) bsum += s_loss[w];

        atomicAdd(&g_lce_acc, (double)bsum);
        __threadfence();
        unsigned int done = atomicAdd(&g_lce_count, 1u);
        if (done == gridDim.x - 1) {
            double total = atomicAdd(&g_lce_acc, 0.0);   // ordered read
            out[0] = (float)(total * (double)inv_b);
            g_lce_acc   = 0.0;                            // reset for next replay
            g_lce_count = 0u;
            __threadfence();
        }
    }
}

extern "C" void kernel_launch(void* const* d_in, const int* in_sizes, int n_in,
                              void* d_out, int out_size)
{
    const float* y_pred = (const float*)d_in[0];
    const int*   y_true = (const int*)d_in[1];
    const float* weight = (const float*)d_in[2];
    const int*   link   = (const int*)d_in[3];
    float* out = (float*)d_out;

    const int B = in_sizes[1];   // 65536

    int grid = (B + WARPS_PER_BLOCK - 1) / WARPS_PER_BLOCK;
    lce_main_kernel<<<grid, WARPS_PER_BLOCK * 32>>>(
        y_pred, y_true, weight, link, out, B, 1.0f / (float)B);
}

// round 15
// speedup vs baseline: 1.1179x; 1.0410x over previous
#include <cuda_runtime.h>
#include <cstdint>
#include <math_constants.h>

// LinkedCrossEntropy, single fused kernel, 1 warp per row:
//   pred    = argmax(y_pred, axis=1)                (first occurrence on ties)
//   penalty = 2 if (pred != y_true && link[y_true, pred]) else 1
//   nll     = -(x[t] - max - log(sum exp(x - max)))
//   out[0]  = mean(penalty * weight[t] * nll)
//
// y_pred: [B, C] f32, y_true: [B] i32, weight: [C] f32, link: [C,C] int32.
// B = 65536, C = 1000.
//
// R14: R10 profile unchanged vs R6 (DRAM 68%, issue 52%) -> the serial cost
// is the two 5-step SHFL trees (~450cyc) + lane-0 dependent load tail
// (~600cyc), not in-register ILP. This round:
//  (a) argmax via fmax tree + monotonic-u32 __reduce_max_sync, then
//      equality-scan + __reduce_min_sync (exact first-occurrence),
//  (b) prefetch t/xt/w with the row loads (warp-uniform broadcasts), issue
//      the link gather BEFORE pass 2 so L2 latency hides under the exp work.

#define LCE_C    1000
#define LCE_VEC  (LCE_C / 4)       // 250 float4 per row
#define WARPS_PER_BLOCK 8

__device__ double       g_lce_acc;    // zero-init at load; reset by last block
__device__ unsigned int g_lce_count;

__device__ __forceinline__ float ex2_approx(float x) {
    float r;
    asm("ex2.approx.f32 %0, %1;" : "=f"(r) : "f"(x));
    return r;
}

// order-preserving f32 -> u32 (no NaNs in data; -inf pads map fine)
__device__ __forceinline__ unsigned f32_mono(float x) {
    unsigned u = __float_as_uint(x);
    return (u & 0x80000000u) ? ~u : (u | 0x80000000u);
}
__device__ __forceinline__ float f32_mono_inv(unsigned u) {
    unsigned b = (u & 0x80000000u) ? (u ^ 0x80000000u) : ~u;
    return __uint_as_float(b);
}

__global__ __launch_bounds__(WARPS_PER_BLOCK * 32)
void lce_main_kernel(const float* __restrict__ y_pred,
                     const int* __restrict__ y_true,
                     const float* __restrict__ weight,
                     const int* __restrict__ link,
                     float* __restrict__ out,
                     int B, float inv_b)
{
    const int warp = threadIdx.x >> 5;
    const int lane = threadIdx.x & 31;
    const int row  = blockIdx.x * WARPS_PER_BLOCK + warp;

    __shared__ float s_loss[WARPS_PER_BLOCK];

    float loss = 0.0f;

    if (row < B) {
        const float4* rp = reinterpret_cast<const float4*>(
            y_pred + (size_t)row * LCE_C);

        // ---- prefetch target index (warp-uniform broadcast, issued with rows)
        const int t = y_true[row];

        // ---- load full row into registers: 8 independent LDG.128 per lane --
        float4 d[8];
        #pragma unroll
        for (int k = 0; k < 8; k++) {
            int v = lane + 32 * k;
            if (v < LCE_VEC) {
                d[k] = rp[v];
            } else {
                d[k] = make_float4(-CUDART_INF_F, -CUDART_INF_F,
                                   -CUDART_INF_F, -CUDART_INF_F);
            }
        }

        // ---- prefetch target logit + weight (uniform; depend only on t) ----
        const float xt = __ldg(y_pred + (size_t)row * LCE_C + t);
        const float w  = weight[t];

        // ---- pass 1a: per-lane max via pure fmax tree (31 FMNMX, depth 5) --
        float q[8];
        #pragma unroll
        for (int k = 0; k < 8; k++)
            q[k] = fmaxf(fmaxf(d[k].x, d[k].y), fmaxf(d[k].z, d[k].w));
        float pm = fmaxf(fmaxf(fmaxf(q[0], q[1]), fmaxf(q[2], q[3])),
                         fmaxf(fmaxf(q[4], q[5]), fmaxf(q[6], q[7])));

        // ---- warp max in ONE redux (monotonic u32) ----
        unsigned um = __reduce_max_sync(0xffffffffu, f32_mono(pm));
        const float m = f32_mono_inv(um);

        // ---- pass 1b: first-occurrence argmax = min index equal to m ----
        int c0 = 0x7fffffff, c1 = 0x7fffffff,
            c2 = 0x7fffffff, c3 = 0x7fffffff;
        #pragma unroll
        for (int k = 0; k < 8; k++) {
            int base = 4 * (lane + 32 * k);
            if (d[k].x == m) c0 = min(c0, base);
            if (d[k].y == m) c1 = min(c1, base + 1);
            if (d[k].z == m) c2 = min(c2, base + 2);
            if (d[k].w == m) c3 = min(c3, base + 3);
        }
        unsigned cand = (unsigned)min(min(c0, c1), min(c2, c3));
        const int am = (int)__reduce_min_sync(0xffffffffu, cand);

        // ---- issue link gather NOW so L2 latency hides under pass 2 ----
        const int linked = link[(size_t)t * LCE_C + am];

        // ---- pass 2: sum exp(x-m) = sum ex2(x*log2e - c); 4 accumulators --
        const float LOG2E = 1.4426950408889634f;
        const float c = m * LOG2E;
        float s0 = 0.0f, s1 = 0.0f, s2 = 0.0f, s3 = 0.0f;
        #pragma unroll
        for (int k = 0; k < 8; k++) {
            float4 x = d[k];
            s0 += ex2_approx(fmaf(x.x, LOG2E, -c));
            s1 += ex2_approx(fmaf(x.y, LOG2E, -c));
            s2 += ex2_approx(fmaf(x.z, LOG2E, -c));
            s3 += ex2_approx(fmaf(x.w, LOG2E, -c));
        }
        float s = (s0 + s1) + (s2 + s3);
        #pragma unroll
        for (int off = 16; off > 0; off >>= 1)
            s += __shfl_xor_sync(0xffffffffu, s, off);

        // ---- lane 0: finalize (all operands already resident) ----
        if (lane == 0) {
            float nll = (m - xt) + __logf(s);
            float pen = (am != t && linked != 0) ? 2.0f : 1.0f;
            loss = pen * w * nll;
        }
    }

    // ---- block reduce: 8 warp losses, one double atomic per block ----
    if (lane == 0) s_loss[warp] = loss;
    __syncthreads();

    if (threadIdx.x == 0) {
        float bsum = 0.0f;
        #pragma unroll
        for (int wIdx = 0; wIdx < WARPS_PER_BLOCK; wIdx++) bsum += s_loss[wIdx];

        atomicAdd(&g_lce_acc, (double)bsum);
        __threadfence();
        unsigned int done = atomicAdd(&g_lce_count, 1u);
        if (done == gridDim.x - 1) {
            double total = atomicAdd(&g_lce_acc, 0.0);   // ordered read
            out[0] = (float)(total * (double)inv_b);
            g_lce_acc   = 0.0;                            // reset for next replay
            g_lce_count = 0u;
            __threadfence();
        }
    }
}

extern "C" void kernel_launch(void* const* d_in, const int* in_sizes, int n_in,
                              void* d_out, int out_size)
{
    const float* y_pred = (const float*)d_in[0];
    const int*   y_true = (const int*)d_in[1];
    const float* weight = (const float*)d_in[2];
    const int*   link   = (const int*)d_in[3];
    float* out = (float*)d_out;

    const int B = in_sizes[1];   // 65536

    int grid = (B + WARPS_PER_BLOCK - 1) / WARPS_PER_BLOCK;
    lce_main_kernel<<<grid, WARPS_PER_BLOCK * 32>>>(
        y_pred, y_true, weight, link, out, B, 1.0f / (float)B);
}